// round 1
// baseline (speedup 1.0000x reference)
#include <cuda_runtime.h>
#include <cuda_bf16.h>

#define NU 339
#define NI 5825
#define NN 6164          // NU + NI
#define BB 32768
#define SS 20
#define DD 128
#define FF 8

// Scratch: l2-normalized node features adj_x (N x D)
__device__ float g_adjx[NN * DD];

// ---------------------------------------------------------------------------
// Kernel A: adj_x = l2norm(user_infos@Wu + bu) ++ l2norm(item_infos@Wi + bi)
// grid = NN blocks, 128 threads (one thread per output dim)
// ---------------------------------------------------------------------------
__global__ __launch_bounds__(DD) void adjx_kernel(
    const float* __restrict__ user_infos, const float* __restrict__ item_infos,
    const float* __restrict__ Wu, const float* __restrict__ bu,
    const float* __restrict__ Wi, const float* __restrict__ bi)
{
    int r = blockIdx.x;
    int d = threadIdx.x;
    const float* feat;
    const float* W;
    const float* bv;
    if (r < NU) { feat = user_infos + r * FF;        W = Wu; bv = bu; }
    else        { feat = item_infos + (r - NU) * FF; W = Wi; bv = bi; }

    float acc = bv[d];
#pragma unroll
    for (int f = 0; f < FF; f++) acc = fmaf(feat[f], W[f * DD + d], acc);

    // block reduction of sum of squares over 128 threads
    __shared__ float red[4];
    float sq = acc * acc;
#pragma unroll
    for (int o = 16; o > 0; o >>= 1) sq += __shfl_xor_sync(0xffffffffu, sq, o);
    if ((threadIdx.x & 31) == 0) red[threadIdx.x >> 5] = sq;
    __syncthreads();
    float tot = red[0] + red[1] + red[2] + red[3];
    float nrm = fmaxf(sqrtf(tot), 1e-12f);
    g_adjx[r * DD + d] = acc / nrm;
}

// ---------------------------------------------------------------------------
// Kernel B: fused per-batch-element pipeline.
// grid = BB blocks, 256 threads.
//   g   = sub_adj @ sub_x                      (20 x 128)
//   h1  = relu(g @ W1 + b1)                    (20 x 256)
//   t2  = sub_adj[roots] @ h1                  (2 x 256)
//   ft  = relu(t2 @ W2 + b2)                   (2 x 128)
//   x   = 0.6*concat(uid,sid) + 0.4*concat(ft0,ft1)    (256)
//   out = relu(relu(relu(x@mW0+mb0)@mW1+mb1)@mW2+mb2)  (1)
// ---------------------------------------------------------------------------
__global__ __launch_bounds__(256) void fused_kernel(
    const int*   __restrict__ user_idx,
    const int*   __restrict__ item_idx,
    const int*   __restrict__ sample_ids,
    const int*   __restrict__ roots,
    const float* __restrict__ adj,
    const float* __restrict__ uid_emb,
    const float* __restrict__ sid_emb,
    const float* __restrict__ W1, const float* __restrict__ b1,
    const float* __restrict__ W2, const float* __restrict__ b2,
    const float* __restrict__ mW0, const float* __restrict__ mb0,
    const float* __restrict__ mW1, const float* __restrict__ mb1,
    const float* __restrict__ mW2, const float* __restrict__ mb2,
    float* __restrict__ out)
{
    const int b   = blockIdx.x;
    const int tid = threadIdx.x;

    __shared__ int   s_sid[SS];
    __shared__ float s_adj[SS][SS];
    __shared__ float s_subx[SS][DD];
    __shared__ float s_g[SS][DD];
    __shared__ float s_h1[SS][2 * DD];
    __shared__ float s_t2[2][2 * DD];
    __shared__ float s_ft[2 * DD];
    __shared__ float s_x[2 * DD];
    __shared__ float s_y1[DD];
    __shared__ float s_y2[64];

    if (tid < SS) s_sid[tid] = sample_ids[b * SS + tid];
    __syncthreads();

    // gather sub_adj (20x20 scattered 4B loads)
    for (int idx = tid; idx < SS * SS; idx += 256) {
        int i = idx / SS, j = idx % SS;
        s_adj[i][j] = __ldg(&adj[(long)s_sid[i] * NN + s_sid[j]]);
    }
    // gather sub_x rows (coalesced float4)
    for (int idx = tid; idx < SS * DD / 4; idx += 256) {
        int i = idx >> 5, q = idx & 31;
        const float4* src = (const float4*)(g_adjx + (long)s_sid[i] * DD);
        ((float4*)s_subx)[idx] = src[q];
    }
    __syncthreads();

    // g = sub_adj @ sub_x   (2560 outputs, dot over 20)
    for (int idx = tid; idx < SS * DD; idx += 256) {
        int i = idx >> 7, d = idx & 127;
        float acc = 0.f;
#pragma unroll
        for (int j = 0; j < SS; j++) acc = fmaf(s_adj[i][j], s_subx[j][d], acc);
        s_g[i][d] = acc;
    }
    __syncthreads();

    // h1 = relu(g @ W1 + b1): thread tid owns output column c = tid (of 256)
    {
        const int c = tid;
        float acc[SS];
        const float bc = __ldg(&b1[c]);
#pragma unroll
        for (int i = 0; i < SS; i++) acc[i] = bc;
        for (int k = 0; k < DD; k += 4) {
            float w0 = __ldg(&W1[(k + 0) * 256 + c]);
            float w1 = __ldg(&W1[(k + 1) * 256 + c]);
            float w2 = __ldg(&W1[(k + 2) * 256 + c]);
            float w3 = __ldg(&W1[(k + 3) * 256 + c]);
#pragma unroll
            for (int i = 0; i < SS; i++) {
                float4 gv = *(const float4*)&s_g[i][k];
                acc[i] = fmaf(gv.x, w0, acc[i]);
                acc[i] = fmaf(gv.y, w1, acc[i]);
                acc[i] = fmaf(gv.z, w2, acc[i]);
                acc[i] = fmaf(gv.w, w3, acc[i]);
            }
        }
#pragma unroll
        for (int i = 0; i < SS; i++) s_h1[i][c] = fmaxf(acc[i], 0.f);
    }
    __syncthreads();

    // t2 = sub_adj[roots] @ h1   (2 x 256), thread = column c
    {
        const int r0 = roots[b * 2 + 0];
        const int r1 = roots[b * 2 + 1];
        const int c  = tid;
        float acc0 = 0.f, acc1 = 0.f;
#pragma unroll
        for (int j = 0; j < SS; j++) {
            float hv = s_h1[j][c];
            acc0 = fmaf(s_adj[r0][j], hv, acc0);
            acc1 = fmaf(s_adj[r1][j], hv, acc1);
        }
        s_t2[0][c] = acc0;
        s_t2[1][c] = acc1;
    }
    __syncthreads();

    // ft = relu(t2 @ W2 + b2)   (2 x 128), 128 active threads
    if (tid < DD) {
        const int d = tid;
        float acc0 = __ldg(&b2[d]);
        float acc1 = acc0;
#pragma unroll 4
        for (int k = 0; k < 2 * DD; k++) {
            float w = __ldg(&W2[k * DD + d]);
            acc0 = fmaf(s_t2[0][k], w, acc0);
            acc1 = fmaf(s_t2[1][k], w, acc1);
        }
        s_ft[d]      = fmaxf(acc0, 0.f);
        s_ft[DD + d] = fmaxf(acc1, 0.f);
    }
    __syncthreads();

    // x = 0.6*id_vec + 0.4*ft_vec
    {
        const int c = tid;
        float idv = (c < DD)
            ? __ldg(&uid_emb[(long)user_idx[b] * DD + c])
            : __ldg(&sid_emb[(long)item_idx[b] * DD + (c - DD)]);
        s_x[c] = 0.6f * idv + 0.4f * s_ft[c];
    }
    __syncthreads();

    // y1 = relu(x @ mW0 + mb0)  (128)
    if (tid < DD) {
        float acc = __ldg(&mb0[tid]);
#pragma unroll 4
        for (int k = 0; k < 2 * DD; k++)
            acc = fmaf(s_x[k], __ldg(&mW0[k * DD + tid]), acc);
        s_y1[tid] = fmaxf(acc, 0.f);
    }
    __syncthreads();

    // y2 = relu(y1 @ mW1 + mb1)  (64)
    if (tid < 64) {
        float acc = __ldg(&mb1[tid]);
#pragma unroll 4
        for (int k = 0; k < DD; k++)
            acc = fmaf(s_y1[k], __ldg(&mW1[k * 64 + tid]), acc);
        s_y2[tid] = fmaxf(acc, 0.f);
    }
    __syncthreads();

    // out = relu(y2 @ mW2 + mb2)  (scalar)
    if (tid < 32) {
        float p = s_y2[tid] * __ldg(&mW2[tid]) +
                  s_y2[tid + 32] * __ldg(&mW2[tid + 32]);
#pragma unroll
        for (int o = 16; o > 0; o >>= 1) p += __shfl_xor_sync(0xffffffffu, p, o);
        if (tid == 0) out[b] = fmaxf(p + __ldg(&mb2[0]), 0.f);
    }
}

// ---------------------------------------------------------------------------
extern "C" void kernel_launch(void* const* d_in, const int* in_sizes, int n_in,
                              void* d_out, int out_size)
{
    const int*   user_indexes = (const int*)  d_in[0];
    const int*   item_indexes = (const int*)  d_in[1];
    const int*   sample_ids   = (const int*)  d_in[2];
    const int*   roots        = (const int*)  d_in[3];
    const float* user_infos   = (const float*)d_in[4];
    const float* item_infos   = (const float*)d_in[5];
    const float* adj_matrix   = (const float*)d_in[6];
    const float* uid_emb      = (const float*)d_in[7];
    const float* sid_emb      = (const float*)d_in[8];
    const float* Wu           = (const float*)d_in[9];
    const float* bu           = (const float*)d_in[10];
    const float* Wi           = (const float*)d_in[11];
    const float* bi           = (const float*)d_in[12];
    const float* W1           = (const float*)d_in[13];
    const float* b1           = (const float*)d_in[14];
    const float* W2           = (const float*)d_in[15];
    const float* b2           = (const float*)d_in[16];
    const float* mW0          = (const float*)d_in[17];
    const float* mb0          = (const float*)d_in[18];
    const float* mW1          = (const float*)d_in[19];
    const float* mb1          = (const float*)d_in[20];
    const float* mW2          = (const float*)d_in[21];
    const float* mb2          = (const float*)d_in[22];
    float* out = (float*)d_out;

    adjx_kernel<<<NN, DD>>>(user_infos, item_infos, Wu, bu, Wi, bi);
    fused_kernel<<<BB, 256>>>(user_indexes, item_indexes, sample_ids, roots,
                              adj_matrix, uid_emb, sid_emb,
                              W1, b1, W2, b2,
                              mW0, mb0, mW1, mb1, mW2, mb2,
                              out);
}

// round 2
// speedup vs baseline: 1.0077x; 1.0077x over previous
#include <cuda_runtime.h>
#include <cuda_bf16.h>

#define NU 339
#define NI 5825
#define NN 6164          // NU + NI
#define BB 32768
#define SS 20
#define DD 128
#define FF 8

// Scratch: l2-normalized node features adj_x (N x D)
__device__ float g_adjx[NN * DD];

// ---------------------------------------------------------------------------
// Kernel A: adj_x = l2norm(user_infos@Wu + bu) ++ l2norm(item_infos@Wi + bi)
// grid = NN blocks, 128 threads (one thread per output dim)
// ---------------------------------------------------------------------------
__global__ __launch_bounds__(DD) void adjx_kernel(
    const float* __restrict__ user_infos, const float* __restrict__ item_infos,
    const float* __restrict__ Wu, const float* __restrict__ bu,
    const float* __restrict__ Wi, const float* __restrict__ bi)
{
    int r = blockIdx.x;
    int d = threadIdx.x;
    const float* feat;
    const float* W;
    const float* bv;
    if (r < NU) { feat = user_infos + r * FF;        W = Wu; bv = bu; }
    else        { feat = item_infos + (r - NU) * FF; W = Wi; bv = bi; }

    float acc = bv[d];
#pragma unroll
    for (int f = 0; f < FF; f++) acc = fmaf(feat[f], W[f * DD + d], acc);

    // block reduction of sum of squares over 128 threads
    __shared__ float red[4];
    float sq = acc * acc;
#pragma unroll
    for (int o = 16; o > 0; o >>= 1) sq += __shfl_xor_sync(0xffffffffu, sq, o);
    if ((threadIdx.x & 31) == 0) red[threadIdx.x >> 5] = sq;
    __syncthreads();
    float tot = red[0] + red[1] + red[2] + red[3];
    float nrm = fmaxf(sqrtf(tot), 1e-12f);
    g_adjx[r * DD + d] = acc / nrm;
}

// ---------------------------------------------------------------------------
// Kernel B: fused per-batch-element pipeline.
// grid = BB blocks, 256 threads.
//   g   = sub_adj @ sub_x                      (20 x 128)
//   h1  = relu(g @ W1 + b1)                    (20 x 256)
//   t2  = sub_adj[roots] @ h1                  (2 x 256)
//   ft  = relu(t2 @ W2 + b2)                   (2 x 128)
//   x   = 0.6*concat(uid,sid) + 0.4*concat(ft0,ft1)    (256)
//   out = relu(relu(relu(x@mW0+mb0)@mW1+mb1)@mW2+mb2)  (1)
// ---------------------------------------------------------------------------
__global__ __launch_bounds__(256) void fused_kernel(
    const int*   __restrict__ user_idx,
    const int*   __restrict__ item_idx,
    const int*   __restrict__ sample_ids,
    const int*   __restrict__ roots,
    const float* __restrict__ adj,
    const float* __restrict__ uid_emb,
    const float* __restrict__ sid_emb,
    const float* __restrict__ W1, const float* __restrict__ b1,
    const float* __restrict__ W2, const float* __restrict__ b2,
    const float* __restrict__ mW0, const float* __restrict__ mb0,
    const float* __restrict__ mW1, const float* __restrict__ mb1,
    const float* __restrict__ mW2, const float* __restrict__ mb2,
    float* __restrict__ out)
{
    const int b   = blockIdx.x;
    const int tid = threadIdx.x;

    __shared__ int   s_sid[SS];
    __shared__ float s_adj[SS][SS];
    __shared__ float s_subx[SS][DD];
    __shared__ float s_g[SS][DD];
    __shared__ float s_h1[SS][2 * DD];
    __shared__ float s_t2[2][2 * DD];
    __shared__ float s_ft[2 * DD];
    __shared__ float s_x[2 * DD];
    __shared__ float s_y1[DD];
    __shared__ float s_y2[64];

    if (tid < SS) s_sid[tid] = sample_ids[b * SS + tid];
    __syncthreads();

    // gather sub_adj (20x20 scattered 4B loads)
    for (int idx = tid; idx < SS * SS; idx += 256) {
        int i = idx / SS, j = idx % SS;
        s_adj[i][j] = __ldg(&adj[(long)s_sid[i] * NN + s_sid[j]]);
    }
    // gather sub_x rows (coalesced float4)
    for (int idx = tid; idx < SS * DD / 4; idx += 256) {
        int i = idx >> 5, q = idx & 31;
        const float4* src = (const float4*)(g_adjx + (long)s_sid[i] * DD);
        ((float4*)s_subx)[idx] = src[q];
    }
    __syncthreads();

    // g = sub_adj @ sub_x   (2560 outputs, dot over 20)
    for (int idx = tid; idx < SS * DD; idx += 256) {
        int i = idx >> 7, d = idx & 127;
        float acc = 0.f;
#pragma unroll
        for (int j = 0; j < SS; j++) acc = fmaf(s_adj[i][j], s_subx[j][d], acc);
        s_g[i][d] = acc;
    }
    __syncthreads();

    // h1 = relu(g @ W1 + b1): thread tid owns output column c = tid (of 256)
    {
        const int c = tid;
        float acc[SS];
        const float bc = __ldg(&b1[c]);
#pragma unroll
        for (int i = 0; i < SS; i++) acc[i] = bc;
        for (int k = 0; k < DD; k += 4) {
            float w0 = __ldg(&W1[(k + 0) * 256 + c]);
            float w1 = __ldg(&W1[(k + 1) * 256 + c]);
            float w2 = __ldg(&W1[(k + 2) * 256 + c]);
            float w3 = __ldg(&W1[(k + 3) * 256 + c]);
#pragma unroll
            for (int i = 0; i < SS; i++) {
                float4 gv = *(const float4*)&s_g[i][k];
                acc[i] = fmaf(gv.x, w0, acc[i]);
                acc[i] = fmaf(gv.y, w1, acc[i]);
                acc[i] = fmaf(gv.z, w2, acc[i]);
                acc[i] = fmaf(gv.w, w3, acc[i]);
            }
        }
#pragma unroll
        for (int i = 0; i < SS; i++) s_h1[i][c] = fmaxf(acc[i], 0.f);
    }
    __syncthreads();

    // t2 = sub_adj[roots] @ h1   (2 x 256), thread = column c
    {
        const int r0 = roots[b * 2 + 0];
        const int r1 = roots[b * 2 + 1];
        const int c  = tid;
        float acc0 = 0.f, acc1 = 0.f;
#pragma unroll
        for (int j = 0; j < SS; j++) {
            float hv = s_h1[j][c];
            acc0 = fmaf(s_adj[r0][j], hv, acc0);
            acc1 = fmaf(s_adj[r1][j], hv, acc1);
        }
        s_t2[0][c] = acc0;
        s_t2[1][c] = acc1;
    }
    __syncthreads();

    // ft = relu(t2 @ W2 + b2)   (2 x 128), 128 active threads
    if (tid < DD) {
        const int d = tid;
        float acc0 = __ldg(&b2[d]);
        float acc1 = acc0;
#pragma unroll 4
        for (int k = 0; k < 2 * DD; k++) {
            float w = __ldg(&W2[k * DD + d]);
            acc0 = fmaf(s_t2[0][k], w, acc0);
            acc1 = fmaf(s_t2[1][k], w, acc1);
        }
        s_ft[d]      = fmaxf(acc0, 0.f);
        s_ft[DD + d] = fmaxf(acc1, 0.f);
    }
    __syncthreads();

    // x = 0.6*id_vec + 0.4*ft_vec
    {
        const int c = tid;
        float idv = (c < DD)
            ? __ldg(&uid_emb[(long)user_idx[b] * DD + c])
            : __ldg(&sid_emb[(long)item_idx[b] * DD + (c - DD)]);
        s_x[c] = 0.6f * idv + 0.4f * s_ft[c];
    }
    __syncthreads();

    // y1 = relu(x @ mW0 + mb0)  (128)
    if (tid < DD) {
        float acc = __ldg(&mb0[tid]);
#pragma unroll 4
        for (int k = 0; k < 2 * DD; k++)
            acc = fmaf(s_x[k], __ldg(&mW0[k * DD + tid]), acc);
        s_y1[tid] = fmaxf(acc, 0.f);
    }
    __syncthreads();

    // y2 = relu(y1 @ mW1 + mb1)  (64)
    if (tid < 64) {
        float acc = __ldg(&mb1[tid]);
#pragma unroll 4
        for (int k = 0; k < DD; k++)
            acc = fmaf(s_y1[k], __ldg(&mW1[k * 64 + tid]), acc);
        s_y2[tid] = fmaxf(acc, 0.f);
    }
    __syncthreads();

    // out = relu(y2 @ mW2 + mb2)  (scalar)
    if (tid < 32) {
        float p = s_y2[tid] * __ldg(&mW2[tid]) +
                  s_y2[tid + 32] * __ldg(&mW2[tid + 32]);
#pragma unroll
        for (int o = 16; o > 0; o >>= 1) p += __shfl_xor_sync(0xffffffffu, p, o);
        if (tid == 0) out[b] = fmaxf(p + __ldg(&mb2[0]), 0.f);
    }
}

// ---------------------------------------------------------------------------
extern "C" void kernel_launch(void* const* d_in, const int* in_sizes, int n_in,
                              void* d_out, int out_size)
{
    const int*   user_indexes = (const int*)  d_in[0];
    const int*   item_indexes = (const int*)  d_in[1];
    const int*   sample_ids   = (const int*)  d_in[2];
    const int*   roots        = (const int*)  d_in[3];
    const float* user_infos   = (const float*)d_in[4];
    const float* item_infos   = (const float*)d_in[5];
    const float* adj_matrix   = (const float*)d_in[6];
    const float* uid_emb      = (const float*)d_in[7];
    const float* sid_emb      = (const float*)d_in[8];
    const float* Wu           = (const float*)d_in[9];
    const float* bu           = (const float*)d_in[10];
    const float* Wi           = (const float*)d_in[11];
    const float* bi           = (const float*)d_in[12];
    const float* W1           = (const float*)d_in[13];
    const float* b1           = (const float*)d_in[14];
    const float* W2           = (const float*)d_in[15];
    const float* b2           = (const float*)d_in[16];
    const float* mW0          = (const float*)d_in[17];
    const float* mb0          = (const float*)d_in[18];
    const float* mW1          = (const float*)d_in[19];
    const float* mb1          = (const float*)d_in[20];
    const float* mW2          = (const float*)d_in[21];
    const float* mb2          = (const float*)d_in[22];
    float* out = (float*)d_out;

    adjx_kernel<<<NN, DD>>>(user_infos, item_infos, Wu, bu, Wi, bi);
    fused_kernel<<<BB, 256>>>(user_indexes, item_indexes, sample_ids, roots,
                              adj_matrix, uid_emb, sid_emb,
                              W1, b1, W2, b2,
                              mW0, mb0, mW1, mb1, mW2, mb2,
                              out);
}

// round 4
// speedup vs baseline: 1.2923x; 1.2824x over previous
#include <cuda_runtime.h>
#include <cuda_bf16.h>

#define NU 339
#define NI 5825
#define NN 6164          // NU + NI
#define BB 32768
#define SS 20
#define DD 128
#define FF 8
#define EPB 4            // elements per GEMM block
#define MT  (EPB * SS)   // 80 rows per block
#define NTILE 128

// Scratch (device globals: allocation-free per harness rules)
__device__ float g_adjx[NN * DD];                  // 3.2 MB
__device__ float g_t2[(size_t)BB * 2 * 256];       // 67 MB

// ---------------------------------------------------------------------------
// Kernel A: adj_x = l2norm(user_infos@Wu + bu) ++ l2norm(item_infos@Wi + bi)
// ---------------------------------------------------------------------------
__global__ __launch_bounds__(DD) void adjx_kernel(
    const float* __restrict__ user_infos, const float* __restrict__ item_infos,
    const float* __restrict__ Wu, const float* __restrict__ bu,
    const float* __restrict__ Wi, const float* __restrict__ bi)
{
    int r = blockIdx.x;
    int d = threadIdx.x;
    const float* feat;
    const float* W;
    const float* bv;
    if (r < NU) { feat = user_infos + r * FF;        W = Wu; bv = bu; }
    else        { feat = item_infos + (r - NU) * FF; W = Wi; bv = bi; }

    float acc = bv[d];
#pragma unroll
    for (int f = 0; f < FF; f++) acc = fmaf(feat[f], W[f * DD + d], acc);

    __shared__ float red[4];
    float sq = acc * acc;
#pragma unroll
    for (int o = 16; o > 0; o >>= 1) sq += __shfl_xor_sync(0xffffffffu, sq, o);
    if ((threadIdx.x & 31) == 0) red[threadIdx.x >> 5] = sq;
    __syncthreads();
    float tot = red[0] + red[1] + red[2] + red[3];
    float nrm = fmaxf(sqrtf(tot), 1e-12f);
    g_adjx[r * DD + d] = acc / nrm;
}

// ---------------------------------------------------------------------------
// Kernel B: fully fused GEMM.
// Per block: 4 elements (80 rows), N-tile 128 (grid.y=2), K=128 in chunks of 32.
//   - gather 4x(20x20) sub_adj + roots
//   - per K-chunk: gather subx rows from g_adjx, build A = sub_adj@subx in smem
//   - main loop: 5x8 register tile, H1 = A@W1 (+b1 preloaded in acc)
//   - epilogue: t2[e][r][c] = sum_rows adj[e][root_r][row]*relu(h1[row][c])
// 256 threads: tx=tid&15 (8 cols), ty=tid>>4 (5 rows).
// ---------------------------------------------------------------------------
__global__ __launch_bounds__(256) void fused_gemm_kernel(
    const int*   __restrict__ sample_ids,
    const int*   __restrict__ roots,
    const float* __restrict__ adj,
    const float* __restrict__ W1, const float* __restrict__ b1)
{
    __shared__ int   s_sid[MT];
    __shared__ int   s_rt[EPB][2];
    __shared__ float s_adj[EPB][SS][SS];     // 6.4 KB
    __shared__ float s_As[MT][33];           // 10.56 KB  (G tile)
    __shared__ float s_subx[MT][36];         // 11.52 KB  (reused as t2 at end)
    __shared__ float s_Bs[32][132];          // 16.9 KB

    const int tid = threadIdx.x;
    const int tx = tid & 15, ty = tid >> 4;
    const int b0 = blockIdx.x * EPB;         // first element of this block
    const int n0 = blockIdx.y * NTILE;

    if (tid < MT) s_sid[tid] = sample_ids[blockIdx.x * MT + tid];
    if (tid < 2 * EPB) s_rt[tid >> 1][tid & 1] = roots[b0 * 2 + tid];
    __syncthreads();

    // gather sub_adj for 4 elements (1600 scattered 4B loads)
    for (int id = tid; id < EPB * SS * SS; id += 256) {
        int e = id / 400, rem = id % 400, i = rem / SS, j = rem % SS;
        s_adj[e][i][j] = __ldg(&adj[(long)s_sid[e * SS + i] * NN + s_sid[e * SS + j]]);
    }

    // acc initialized with bias
    float acc[5][8];
    {
        float4 bv0 = *(const float4*)&b1[n0 + tx * 8];
        float4 bv1 = *(const float4*)&b1[n0 + tx * 8 + 4];
#pragma unroll
        for (int i = 0; i < 5; i++) {
            acc[i][0] = bv0.x; acc[i][1] = bv0.y; acc[i][2] = bv0.z; acc[i][3] = bv0.w;
            acc[i][4] = bv1.x; acc[i][5] = bv1.y; acc[i][6] = bv1.z; acc[i][7] = bv1.w;
        }
    }

    for (int k0 = 0; k0 < DD; k0 += 32) {
        // gather subx rows: 80 rows x 32 k (640 float4, coalesced per row)
        for (int id = tid; id < MT * 8; id += 256) {
            int row = id >> 3, q = id & 7;
            *(float4*)&s_subx[row][q * 4] =
                *(const float4*)&g_adjx[(long)s_sid[row] * DD + k0 + q * 4];
        }
        // load W1 tile: 32 k x 128 n (1024 float4, coalesced)
        for (int id = tid; id < 1024; id += 256) {
            int k = id >> 5, cq = id & 31;
            *(float4*)&s_Bs[k][cq * 4] =
                *(const float4*)&W1[(long)(k0 + k) * 256 + n0 + cq * 4];
        }
        __syncthreads();

        // build A tile: As[row][kk] = sum_j adj[e][i][j] * subx[e*20+j][kk]
        for (int id = tid; id < MT * 32; id += 256) {
            int row = id >> 5, kk = id & 31;
            int e = row / SS, il = row % SS;
            float a = 0.f;
#pragma unroll
            for (int j = 0; j < SS; j++)
                a = fmaf(s_adj[e][il][j], s_subx[e * SS + j][kk], a);
            s_As[row][kk] = a;
        }
        __syncthreads();

        // main: 5x8 register tile over 32 k
#pragma unroll 4
        for (int kk = 0; kk < 32; kk++) {
            float a[5], bb[8];
#pragma unroll
            for (int i = 0; i < 5; i++) a[i] = s_As[ty * 5 + i][kk];
            *(float4*)&bb[0] = *(const float4*)&s_Bs[kk][tx * 8];
            *(float4*)&bb[4] = *(const float4*)&s_Bs[kk][tx * 8 + 4];
#pragma unroll
            for (int i = 0; i < 5; i++)
#pragma unroll
                for (int j = 0; j < 8; j++)
                    acc[i][j] = fmaf(a[i], bb[j], acc[i][j]);
        }
        __syncthreads();
    }

    // ---- epilogue: t2 reduction (reuse s_subx storage) ----
    float* t2s = &s_subx[0][0];              // 1024 floats: [e*2+r][c]
    for (int id = tid; id < EPB * 2 * NTILE; id += 256) t2s[id] = 0.f;
    __syncthreads();

    {
        const int e = ty >> 2;               // 4 ty-groups per element
        const int il0 = (ty & 3) * 5;        // local row base within element
#pragma unroll
        for (int r = 0; r < 2; r++) {
            const int rt = s_rt[e][r];
            float part[8] = {0.f, 0.f, 0.f, 0.f, 0.f, 0.f, 0.f, 0.f};
#pragma unroll
            for (int i = 0; i < 5; i++) {
                float w = s_adj[e][rt][il0 + i];
#pragma unroll
                for (int j = 0; j < 8; j++)
                    part[j] = fmaf(w, fmaxf(acc[i][j], 0.f), part[j]);
            }
#pragma unroll
            for (int j = 0; j < 8; j++)
                atomicAdd(&t2s[(e * 2 + r) * NTILE + tx * 8 + j], part[j]);
        }
    }
    __syncthreads();

    // write t2 tile to global: g_t2[(b0+e)*512 + r*256 + n0 + c]
    for (int id = tid; id < EPB * 2 * NTILE; id += 256) {
        int er = id >> 7, c = id & 127;
        g_t2[((long)b0 + (er >> 1)) * 512 + (er & 1) * 256 + n0 + c] = t2s[id];
    }
}

// ---------------------------------------------------------------------------
// Kernel C: per element tail.
//   ft = relu(t2 @ W2 + b2)  (2 x 128)
//   x  = 0.6*id_vec + 0.4*ft_vec
//   out = MLP(x)
// ---------------------------------------------------------------------------
__global__ __launch_bounds__(256) void tail_kernel(
    const int*   __restrict__ user_idx,
    const int*   __restrict__ item_idx,
    const float* __restrict__ uid_emb,
    const float* __restrict__ sid_emb,
    const float* __restrict__ W2, const float* __restrict__ b2,
    const float* __restrict__ mW0, const float* __restrict__ mb0,
    const float* __restrict__ mW1, const float* __restrict__ mb1,
    const float* __restrict__ mW2, const float* __restrict__ mb2,
    float* __restrict__ out)
{
    const int b = blockIdx.x, tid = threadIdx.x;
    __shared__ float s_t2[2][256];
    __shared__ float s_x[256];
    __shared__ float s_part[2][128];
    __shared__ float s_y1[128];
    __shared__ float s_p2[4][64];
    __shared__ float s_y2[64];
    __shared__ float s_red[2];

    ((float*)s_t2)[tid]       = g_t2[(long)b * 512 + tid];
    ((float*)s_t2)[tid + 256] = g_t2[(long)b * 512 + tid + 256];
    __syncthreads();

    // ft + merge: 256 outputs = (root r, dim d)
    {
        int r = tid >> 7, d = tid & 127;
        float acc = __ldg(&b2[d]);
#pragma unroll 4
        for (int k = 0; k < 2 * DD; k++)
            acc = fmaf(s_t2[r][k], __ldg(&W2[k * DD + d]), acc);
        float ft = fmaxf(acc, 0.f);
        float idv = (r == 0)
            ? __ldg(&uid_emb[(long)user_idx[b] * DD + d])
            : __ldg(&sid_emb[(long)item_idx[b] * DD + d]);
        s_x[tid] = 0.6f * idv + 0.4f * ft;
    }
    __syncthreads();

    // MLP0: 128 outputs, 2-way split-k
    {
        int o = tid & 127, h = tid >> 7;
        float acc = 0.f;
#pragma unroll 4
        for (int k = h * 128; k < h * 128 + 128; k++)
            acc = fmaf(s_x[k], __ldg(&mW0[k * 128 + o]), acc);
        s_part[h][o] = acc;
    }
    __syncthreads();
    if (tid < 128)
        s_y1[tid] = fmaxf(s_part[0][tid] + s_part[1][tid] + __ldg(&mb0[tid]), 0.f);
    __syncthreads();

    // MLP1: 64 outputs, 4-way split-k
    {
        int o = tid & 63, q = tid >> 6;
        float acc = 0.f;
#pragma unroll
        for (int k = q * 32; k < q * 32 + 32; k++)
            acc = fmaf(s_y1[k], __ldg(&mW1[k * 64 + o]), acc);
        s_p2[q][o] = acc;
    }
    __syncthreads();
    if (tid < 64)
        s_y2[tid] = fmaxf(s_p2[0][tid] + s_p2[1][tid] + s_p2[2][tid] +
                          s_p2[3][tid] + __ldg(&mb1[tid]), 0.f);
    __syncthreads();

    // MLP2: scalar
    if (tid < 64) {
        float p = s_y2[tid] * __ldg(&mW2[tid]);
#pragma unroll
        for (int o = 16; o > 0; o >>= 1) p += __shfl_xor_sync(0xffffffffu, p, o);
        if ((tid & 31) == 0) s_red[tid >> 5] = p;
    }
    __syncthreads();
    if (tid == 0) out[b] = fmaxf(s_red[0] + s_red[1] + __ldg(&mb2[0]), 0.f);
}

// ---------------------------------------------------------------------------
extern "C" void kernel_launch(void* const* d_in, const int* in_sizes, int n_in,
                              void* d_out, int out_size)
{
    const int*   user_indexes = (const int*)  d_in[0];
    const int*   item_indexes = (const int*)  d_in[1];
    const int*   sample_ids   = (const int*)  d_in[2];
    const int*   roots        = (const int*)  d_in[3];
    const float* user_infos   = (const float*)d_in[4];
    const float* item_infos   = (const float*)d_in[5];
    const float* adj_matrix   = (const float*)d_in[6];
    const float* uid_emb      = (const float*)d_in[7];
    const float* sid_emb      = (const float*)d_in[8];
    const float* Wu           = (const float*)d_in[9];
    const float* bu           = (const float*)d_in[10];
    const float* Wi           = (const float*)d_in[11];
    const float* bi           = (const float*)d_in[12];
    const float* W1           = (const float*)d_in[13];
    const float* b1           = (const float*)d_in[14];
    const float* W2           = (const float*)d_in[15];
    const float* b2           = (const float*)d_in[16];
    const float* mW0          = (const float*)d_in[17];
    const float* mb0          = (const float*)d_in[18];
    const float* mW1          = (const float*)d_in[19];
    const float* mb1          = (const float*)d_in[20];
    const float* mW2          = (const float*)d_in[21];
    const float* mb2          = (const float*)d_in[22];
    float* out = (float*)d_out;

    adjx_kernel<<<NN, DD>>>(user_infos, item_infos, Wu, bu, Wi, bi);
    fused_gemm_kernel<<<dim3(BB / EPB, 2), 256>>>(sample_ids, roots, adj_matrix,
                                                  W1, b1);
    tail_kernel<<<BB, 256>>>(user_indexes, item_indexes, uid_emb, sid_emb,
                             W2, b2, mW0, mb0, mW1, mb1, mW2, mb2,
                             out);
}